// round 5
// baseline (speedup 1.0000x reference)
#include <cuda_runtime.h>
#include <cuda_fp16.h>
#include <stdint.h>

// Inputs: queries f32 (4,512,256), keys f32 (4,512,256), values f32 (4,512,256),
// Wq f32 (256,256), Wk f32 (256,256), wv f32 (256), valid_lens i32 (4).
// Output: f32 (4,512,256).

constexpr int B_ = 4, Q_ = 512, K_ = 512, D_ = 256, H_ = 256;

// Projections stored as fp16, TRANSPOSED: [b][h][q] / [b][h][k]
__device__ __half g_qh[B_ * H_ * Q_];         // 1 MB
__device__ __half g_kh[B_ * H_ * K_];         // 1 MB
__device__ float  g_scores[B_ * Q_ * K_];     // 4 MB (scores -> probs in-place)

__device__ __forceinline__ __half2 htanh2(__half2 x) {
    uint32_t xi = *reinterpret_cast<uint32_t*>(&x), yi;
    asm("tanh.approx.f16x2 %0, %1;" : "=r"(yi) : "r"(xi));
    return *reinterpret_cast<__half2*>(&yi);
}

// ---------------------------------------------------------------------------
// Both projections in ONE launch (z=0: queries@Wq, z=1: keys@Wk).
// fp32 64x64x16 tiled GEMM, 4x4 per thread; epilogue converts to fp16 and
// stores TRANSPOSED into [b][h][q].
// ---------------------------------------------------------------------------
__global__ __launch_bounds__(256) void proj_kernel(
    const float* __restrict__ Qin, const float* __restrict__ Kin,
    const float* __restrict__ Wq,  const float* __restrict__ Wk)
{
    constexpr int BM = 64, BN = 64, BK = 16;
    __shared__ float As[BK][BM + 4];
    __shared__ float Bs[BK][BN];

    const float* A  = blockIdx.z ? Kin : Qin;
    const float* Bm = blockIdx.z ? Wk  : Wq;
    __half*      Ct = blockIdx.z ? g_kh : g_qh;

    const int t  = threadIdx.x;
    const int tx = t & 15;
    const int ty = t >> 4;
    const int m0 = blockIdx.y * BM;     // global row in (B*Q)
    const int n0 = blockIdx.x * BN;     // h

    float acc[4][4] = {};

    for (int k0 = 0; k0 < D_; k0 += BK) {
        {   int r  = t >> 2;
            int c4 = (t & 3) << 2;
            float4 v = *(const float4*)(A + (long)(m0 + r) * D_ + k0 + c4);
            As[c4 + 0][r] = v.x; As[c4 + 1][r] = v.y;
            As[c4 + 2][r] = v.z; As[c4 + 3][r] = v.w;
        }
        {   int r  = t >> 4;
            int c4 = (t & 15) << 2;
            *(float4*)(&Bs[r][c4]) =
                *(const float4*)(Bm + (long)(k0 + r) * H_ + n0 + c4);
        }
        __syncthreads();

        #pragma unroll
        for (int kk = 0; kk < BK; kk++) {
            float4 a4 = *(const float4*)(&As[kk][ty << 2]);
            float4 b4 = *(const float4*)(&Bs[kk][tx << 2]);
            float a[4] = {a4.x, a4.y, a4.z, a4.w};
            float b[4] = {b4.x, b4.y, b4.z, b4.w};
            #pragma unroll
            for (int i = 0; i < 4; i++)
                #pragma unroll
                for (int j = 0; j < 4; j++)
                    acc[i][j] += a[i] * b[j];
        }
        __syncthreads();
    }

    // Transposed half store: Ct[b][h = n0+tx*4+j][q = q0b + ty*4 + i]
    const int b   = m0 >> 9;          // Q_ == 512
    const int q0b = (m0 & 511) + (ty << 2);
    __half* base = Ct + (long)b * H_ * Q_ + q0b;
    #pragma unroll
    for (int j = 0; j < 4; j++) {
        __half2 lo = __floats2half2_rn(acc[0][j], acc[1][j]);
        __half2 hi = __floats2half2_rn(acc[2][j], acc[3][j]);
        __half2* dst = (__half2*)(base + (long)(n0 + (tx << 2) + j) * Q_);
        dst[0] = lo;
        dst[1] = hi;
    }
}

// ---------------------------------------------------------------------------
// scores[b,q,k] = sum_h wv[h] * tanh(qproj[q,h] + kproj[k,h]) via f16x2 tanh.
// Tiles: 32q x 64k, 256 thr, thread = 2q (half2) x 4k. h chunks of 32.
// Projections arrive transposed [h][q]/[h][k] so smem loads are coalesced.
// ---------------------------------------------------------------------------
__global__ __launch_bounds__(256) void scores_kernel(
    const float* __restrict__ wv, const int* __restrict__ valid)
{
    constexpr int TQ = 32, TK = 64, HC = 32;
    __shared__ __half qs_t[HC][TQ];     // [h][q]  64B rows
    __shared__ __half ks_t[HC][TK];     // [h][k] 128B rows
    __shared__ float  wvs[H_];

    const int b  = blockIdx.z;
    const int q0 = blockIdx.y * TQ;
    const int k0 = blockIdx.x * TK;
    const int L  = valid[b];
    if (k0 >= L) return;

    const int t  = threadIdx.x;
    const int tx = t & 15;              // k quad
    const int ty = t >> 4;              // q pair

    wvs[t] = wv[t];

    const __half* qp = g_qh + ((long)b * H_) * Q_ + q0;
    const __half* kp = g_kh + ((long)b * H_) * K_ + k0;

    float acc[2][4] = {};

    for (int hc = 0; hc < H_; hc += HC) {
        {   // q tile: 32h x 32q halves; 4 halves (8B) per thread
            int r = t >> 3, c = (t & 7) << 2;
            *(uint2*)&qs_t[r][c] =
                *(const uint2*)(qp + (long)(hc + r) * Q_ + c);
        }
        {   // k tile: 32h x 64k halves; 8 halves (16B) per thread
            int r = t >> 3, c = (t & 7) << 3;
            *(uint4*)&ks_t[r][c] =
                *(const uint4*)(kp + (long)(hc + r) * K_ + c);
        }
        __syncthreads();

        #pragma unroll 8
        for (int h = 0; h < HC; h++) {
            float   w  = wvs[hc + h];
            __half2 q2 = *(const __half2*)&qs_t[h][ty << 1];       // (q0,q1)
            __half2 kA = *(const __half2*)&ks_t[h][(tx << 2) + 0]; // (k0,k1)
            __half2 kB = *(const __half2*)&ks_t[h][(tx << 2) + 2]; // (k2,k3)

            float2 f;
            f = __half22float2(htanh2(__hadd2(q2, __low2half2 (kA))));
            acc[0][0] += w * f.x;  acc[1][0] += w * f.y;
            f = __half22float2(htanh2(__hadd2(q2, __high2half2(kA))));
            acc[0][1] += w * f.x;  acc[1][1] += w * f.y;
            f = __half22float2(htanh2(__hadd2(q2, __low2half2 (kB))));
            acc[0][2] += w * f.x;  acc[1][2] += w * f.y;
            f = __half22float2(htanh2(__hadd2(q2, __high2half2(kB))));
            acc[0][3] += w * f.x;  acc[1][3] += w * f.y;
        }
        __syncthreads();
    }

    float* srow = g_scores + ((long)b * Q_ + q0 + (ty << 1)) * K_ + k0 + (tx << 2);
    *(float4*)(srow)      = make_float4(acc[0][0], acc[0][1], acc[0][2], acc[0][3]);
    *(float4*)(srow + K_) = make_float4(acc[1][0], acc[1][1], acc[1][2], acc[1][3]);
}

// ---------------------------------------------------------------------------
// Warp-per-row masked softmax, in-place; exact 0 for k >= L.
// ---------------------------------------------------------------------------
__global__ __launch_bounds__(256) void softmax_kernel(const int* __restrict__ valid)
{
    const int warp = threadIdx.x >> 5;
    const int lane = threadIdx.x & 31;
    const int row  = blockIdx.x * 8 + warp;
    const int b    = row >> 9;
    const int L    = valid[b];
    float* p = g_scores + (long)row * K_;

    float s[16];
    float m = -INFINITY;
    #pragma unroll
    for (int i = 0; i < 16; i++) {
        int idx = lane + (i << 5);
        s[i] = (idx < L) ? p[idx] : -INFINITY;
        m = fmaxf(m, s[i]);
    }
    #pragma unroll
    for (int o = 16; o; o >>= 1) m = fmaxf(m, __shfl_xor_sync(0xffffffffu, m, o));

    float sum = 0.0f;
    #pragma unroll
    for (int i = 0; i < 16; i++) {
        s[i] = (s[i] == -INFINITY) ? 0.0f : __expf(s[i] - m);
        sum += s[i];
    }
    #pragma unroll
    for (int o = 16; o; o >>= 1) sum += __shfl_xor_sync(0xffffffffu, sum, o);
    const float inv = 1.0f / sum;

    #pragma unroll
    for (int i = 0; i < 16; i++) p[lane + (i << 5)] = s[i] * inv;
}

// ---------------------------------------------------------------------------
// out = probs @ values. BM=BN=BK=32 -> 512 blocks (2x occupancy vs R3).
// Ps kept row-major: P read as sequential float4 per thread (no transpose).
// k-tiles beyond valid_len skipped (probs are exact zeros there).
// ---------------------------------------------------------------------------
__global__ __launch_bounds__(256) void av_kernel(
    const float* __restrict__ V, const int* __restrict__ valid,
    float* __restrict__ out)
{
    constexpr int BM = 32, BN = 32, BK = 32;
    __shared__ float Ps[BM][BK];        // [m][k], rows 128B
    __shared__ float Vs[BK][BN];        // [k][n]

    const int b = blockIdx.z;
    const int L = valid[b];
    const float* P  = g_scores + (long)b * Q_ * K_;
    const float* Vb = V + (long)b * K_ * D_;
    float*       C  = out + (long)b * Q_ * D_;

    const int t  = threadIdx.x;
    const int tx = t & 7;               // n quad: cols tx*4..tx*4+3
    const int ty = t >> 3;              // m row 0..31
    const int m0 = blockIdx.y * BM;
    const int n0 = blockIdx.x * BN;

    const int r = t >> 3, c4 = (t & 7) << 2;   // loader coords (1 float4 each)

    float acc[4] = {};

    for (int k0 = 0; k0 < L; k0 += BK) {
        *(float4*)&Ps[r][c4] = *(const float4*)(P  + (long)(m0 + r) * K_ + k0 + c4);
        *(float4*)&Vs[r][c4] = *(const float4*)(Vb + (long)(k0 + r) * D_ + n0 + c4);
        __syncthreads();

        #pragma unroll
        for (int kg = 0; kg < BK; kg += 4) {
            float4 p4 = *(const float4*)&Ps[ty][kg];
            float4 v0 = *(const float4*)&Vs[kg + 0][tx << 2];
            float4 v1 = *(const float4*)&Vs[kg + 1][tx << 2];
            float4 v2 = *(const float4*)&Vs[kg + 2][tx << 2];
            float4 v3 = *(const float4*)&Vs[kg + 3][tx << 2];
            acc[0] += p4.x*v0.x + p4.y*v1.x + p4.z*v2.x + p4.w*v3.x;
            acc[1] += p4.x*v0.y + p4.y*v1.y + p4.z*v2.y + p4.w*v3.y;
            acc[2] += p4.x*v0.z + p4.y*v1.z + p4.z*v2.z + p4.w*v3.z;
            acc[3] += p4.x*v0.w + p4.y*v1.w + p4.z*v2.w + p4.w*v3.w;
        }
        __syncthreads();
    }

    *(float4*)(C + (long)(m0 + ty) * D_ + n0 + (tx << 2)) =
        make_float4(acc[0], acc[1], acc[2], acc[3]);
}

// ---------------------------------------------------------------------------
extern "C" void kernel_launch(void* const* d_in, const int* in_sizes, int n_in,
                              void* d_out, int out_size)
{
    const float* queries = (const float*)d_in[0];
    const float* keys    = (const float*)d_in[1];
    const float* values  = (const float*)d_in[2];
    const float* Wq      = (const float*)d_in[3];
    const float* Wk      = (const float*)d_in[4];
    const float* wv      = (const float*)d_in[5];
    const int*   valid   = (const int*)d_in[6];
    float* out = (float*)d_out;
    (void)in_sizes; (void)n_in; (void)out_size;

    // 1) both projections (fp32 GEMM -> fp16 transposed store), one launch
    proj_kernel<<<dim3(H_ / 64, (B_ * Q_) / 64, 2), 256>>>(queries, keys, Wq, Wk);

    // 2) fused tanh scores via tanh.approx.f16x2, masked tiles skipped
    scores_kernel<<<dim3(K_ / 64, Q_ / 32, B_), 256>>>(wv, valid);

    // 3) warp-per-row masked softmax (zeros beyond L)
    softmax_kernel<<<dim3((B_ * Q_) / 8), 256>>>(valid);

    // 4) out = probs @ values, 512 blocks, masked k-tiles skipped
    av_kernel<<<dim3(D_ / 32, Q_ / 32, B_), 256>>>(values, valid, out);
}

// round 13
// speedup vs baseline: 1.0724x; 1.0724x over previous
#include <cuda_runtime.h>
#include <cuda_fp16.h>
#include <stdint.h>

// Inputs: queries f32 (4,512,256), keys f32 (4,512,256), values f32 (4,512,256),
// Wq f32 (256,256), Wk f32 (256,256), wv f32 (256), valid_lens i32 (4).
// Output: f32 (4,512,256).

constexpr int B_ = 4, Q_ = 512, K_ = 512, D_ = 256, H_ = 256;

// Projections stored as fp16, TRANSPOSED: [b][h][q] / [b][h][k]
__device__ __half g_qh[B_ * H_ * Q_];         // 1 MB
__device__ __half g_kh[B_ * H_ * K_];         // 1 MB
__device__ float  g_scores[B_ * Q_ * K_];     // 4 MB (scores -> probs in-place)

__device__ __forceinline__ __half2 htanh2(__half2 x) {
    uint32_t xi = *reinterpret_cast<uint32_t*>(&x), yi;
    asm("tanh.approx.f16x2 %0, %1;" : "=r"(yi) : "r"(xi));
    return *reinterpret_cast<__half2*>(&yi);
}

// ---------------------------------------------------------------------------
// Both projections in ONE launch (z=0: queries@Wq, z=1: keys@Wk).
// fp32 64x64x16 tiled GEMM, 4x4 per thread. Epilogue stages the 64(m)x64(h)
// tile through smem as fp16 and writes [b][h][q] with fully COALESCED
// 128B-row stores (R5's direct scatter wasted 3/4 of each sector).
// ---------------------------------------------------------------------------
__global__ __launch_bounds__(256) void proj_kernel(
    const float* __restrict__ Qin, const float* __restrict__ Kin,
    const float* __restrict__ Wq,  const float* __restrict__ Wk)
{
    constexpr int BM = 64, BN = 64, BK = 16;
    __shared__ float As[BK][BM + 4];
    __shared__ float Bs[BK][BN];
    __shared__ __half ht[BN][BM + 8];   // [h][m], row = 144B (16B-aligned)

    const float* A  = blockIdx.z ? Kin : Qin;
    const float* Bm = blockIdx.z ? Wk  : Wq;
    __half*      Ct = blockIdx.z ? g_kh : g_qh;

    const int t  = threadIdx.x;
    const int tx = t & 15;
    const int ty = t >> 4;
    const int m0 = blockIdx.y * BM;     // global row in (B*Q)
    const int n0 = blockIdx.x * BN;     // h

    float acc[4][4] = {};

    for (int k0 = 0; k0 < D_; k0 += BK) {
        {   int r  = t >> 2;
            int c4 = (t & 3) << 2;
            float4 v = *(const float4*)(A + (long)(m0 + r) * D_ + k0 + c4);
            As[c4 + 0][r] = v.x; As[c4 + 1][r] = v.y;
            As[c4 + 2][r] = v.z; As[c4 + 3][r] = v.w;
        }
        {   int r  = t >> 4;
            int c4 = (t & 15) << 2;
            *(float4*)(&Bs[r][c4]) =
                *(const float4*)(Bm + (long)(k0 + r) * H_ + n0 + c4);
        }
        __syncthreads();

        #pragma unroll
        for (int kk = 0; kk < BK; kk++) {
            float4 a4 = *(const float4*)(&As[kk][ty << 2]);
            float4 b4 = *(const float4*)(&Bs[kk][tx << 2]);
            float a[4] = {a4.x, a4.y, a4.z, a4.w};
            float b[4] = {b4.x, b4.y, b4.z, b4.w};
            #pragma unroll
            for (int i = 0; i < 4; i++)
                #pragma unroll
                for (int j = 0; j < 4; j++)
                    acc[i][j] += a[i] * b[j];
        }
        __syncthreads();
    }

    // Stage transposed half tile: ht[h_local = tx*4+j][m_local = ty*4+i]
    #pragma unroll
    for (int j = 0; j < 4; j++)
        #pragma unroll
        for (int i = 0; i < 4; i++)
            ht[(tx << 2) + j][(ty << 2) + i] = __float2half(acc[i][j]);
    __syncthreads();

    // Coalesced copy-out: each row of ht (64 halves = 128B) -> [b][h][q]
    const int b  = m0 >> 9;             // Q_ == 512
    const int q0 = m0 & 511;
    __half* dstbase = Ct + (long)b * H_ * Q_ + q0;
    const int rr = t >> 3;              // 0..31
    const int cc = (t & 7) << 3;        // halves, 16B chunks
    #pragma unroll
    for (int pass = 0; pass < 2; pass++) {
        int r = rr + (pass << 5);
        *(uint4*)(dstbase + (long)(n0 + r) * Q_ + cc) = *(const uint4*)&ht[r][cc];
    }
}

// ---------------------------------------------------------------------------
// scores[b,q,k] = sum_h wv[h] * tanh(qproj[q,h] + kproj[k,h]) via f16x2 tanh.
// Tiles: 32q x 64k, 256 thr, thread = 2q (half2) x 4k. h chunks of 32.
// Projections arrive transposed [h][q]/[h][k] so smem loads are coalesced.
// ---------------------------------------------------------------------------
__global__ __launch_bounds__(256) void scores_kernel(
    const float* __restrict__ wv, const int* __restrict__ valid)
{
    constexpr int TQ = 32, TK = 64, HC = 32;
    __shared__ __half qs_t[HC][TQ];     // [h][q]  64B rows
    __shared__ __half ks_t[HC][TK];     // [h][k] 128B rows
    __shared__ float  wvs[H_];

    const int b  = blockIdx.z;
    const int q0 = blockIdx.y * TQ;
    const int k0 = blockIdx.x * TK;
    const int L  = valid[b];
    if (k0 >= L) return;

    const int t  = threadIdx.x;
    const int tx = t & 15;              // k quad
    const int ty = t >> 4;              // q pair

    wvs[t] = wv[t];

    const __half* qp = g_qh + ((long)b * H_) * Q_ + q0;
    const __half* kp = g_kh + ((long)b * H_) * K_ + k0;

    float acc[2][4] = {};

    for (int hc = 0; hc < H_; hc += HC) {
        {   // q tile: 32h x 32q halves; 4 halves (8B) per thread
            int r = t >> 3, c = (t & 7) << 2;
            *(uint2*)&qs_t[r][c] =
                *(const uint2*)(qp + (long)(hc + r) * Q_ + c);
        }
        {   // k tile: 32h x 64k halves; 8 halves (16B) per thread
            int r = t >> 3, c = (t & 7) << 3;
            *(uint4*)&ks_t[r][c] =
                *(const uint4*)(kp + (long)(hc + r) * K_ + c);
        }
        __syncthreads();

        #pragma unroll 8
        for (int h = 0; h < HC; h++) {
            float   w  = wvs[hc + h];
            __half2 q2 = *(const __half2*)&qs_t[h][ty << 1];       // (q0,q1)
            __half2 kA = *(const __half2*)&ks_t[h][(tx << 2) + 0]; // (k0,k1)
            __half2 kB = *(const __half2*)&ks_t[h][(tx << 2) + 2]; // (k2,k3)

            float2 f;
            f = __half22float2(htanh2(__hadd2(q2, __low2half2 (kA))));
            acc[0][0] += w * f.x;  acc[1][0] += w * f.y;
            f = __half22float2(htanh2(__hadd2(q2, __high2half2(kA))));
            acc[0][1] += w * f.x;  acc[1][1] += w * f.y;
            f = __half22float2(htanh2(__hadd2(q2, __low2half2 (kB))));
            acc[0][2] += w * f.x;  acc[1][2] += w * f.y;
            f = __half22float2(htanh2(__hadd2(q2, __high2half2(kB))));
            acc[0][3] += w * f.x;  acc[1][3] += w * f.y;
        }
        __syncthreads();
    }

    float* srow = g_scores + ((long)b * Q_ + q0 + (ty << 1)) * K_ + k0 + (tx << 2);
    *(float4*)(srow)      = make_float4(acc[0][0], acc[0][1], acc[0][2], acc[0][3]);
    *(float4*)(srow + K_) = make_float4(acc[1][0], acc[1][1], acc[1][2], acc[1][3]);
}

// ---------------------------------------------------------------------------
// Warp-per-row masked softmax, in-place; exact 0 for k >= L.
// ---------------------------------------------------------------------------
__global__ __launch_bounds__(256) void softmax_kernel(const int* __restrict__ valid)
{
    const int warp = threadIdx.x >> 5;
    const int lane = threadIdx.x & 31;
    const int row  = blockIdx.x * 8 + warp;
    const int b    = row >> 9;
    const int L    = valid[b];
    float* p = g_scores + (long)row * K_;

    float s[16];
    float m = -INFINITY;
    #pragma unroll
    for (int i = 0; i < 16; i++) {
        int idx = lane + (i << 5);
        s[i] = (idx < L) ? p[idx] : -INFINITY;
        m = fmaxf(m, s[i]);
    }
    #pragma unroll
    for (int o = 16; o; o >>= 1) m = fmaxf(m, __shfl_xor_sync(0xffffffffu, m, o));

    float sum = 0.0f;
    #pragma unroll
    for (int i = 0; i < 16; i++) {
        s[i] = (s[i] == -INFINITY) ? 0.0f : __expf(s[i] - m);
        sum += s[i];
    }
    #pragma unroll
    for (int o = 16; o; o >>= 1) sum += __shfl_xor_sync(0xffffffffu, sum, o);
    const float inv = 1.0f / sum;

    #pragma unroll
    for (int i = 0; i < 16; i++) p[lane + (i << 5)] = s[i] * inv;
}

// ---------------------------------------------------------------------------
// out = probs @ values. BM=BN=64, BK=32, 4x4 per thread: 2 LDS.128 per
// 16 FFMA (2B/FFMA) so the smem crossbar (128B/cyc) exactly feeds the fma
// pipe (64 FFMA/cyc) -- fixes R5's smem-bound 6B/FFMA design.
// k-tiles beyond valid_len skipped (probs there are exact zeros).
// ---------------------------------------------------------------------------
__global__ __launch_bounds__(256) void av_kernel(
    const float* __restrict__ V, const int* __restrict__ valid,
    float* __restrict__ out)
{
    constexpr int BM = 64, BN = 64, BK = 32;
    __shared__ float PsT[BK][BM + 4];   // [k][m], row 272B (16B-aligned)
    __shared__ float Vs[BK][BN + 4];    // [k][n], row 272B

    const int b = blockIdx.z;
    const int L = valid[b];
    const float* P  = g_scores + (long)b * Q_ * K_;
    const float* Vb = V + (long)b * K_ * D_;
    float*       C  = out + (long)b * Q_ * D_;

    const int t  = threadIdx.x;
    const int tx = t & 15;              // n quad
    const int ty = t >> 4;              // m quad
    const int m0 = blockIdx.y * BM;
    const int n0 = blockIdx.x * BN;

    float acc[4][4] = {};

    for (int k0 = 0; k0 < L; k0 += BK) {
        {   // P tile 64m x 32k -> transposed PsT[k][m]; 8 floats/thread
            int r = t >> 2, c = (t & 3) << 3;
            const float* src = P + (long)(m0 + r) * K_ + k0 + c;
            float4 v0 = *(const float4*)(src);
            float4 v1 = *(const float4*)(src + 4);
            PsT[c + 0][r] = v0.x; PsT[c + 1][r] = v0.y;
            PsT[c + 2][r] = v0.z; PsT[c + 3][r] = v0.w;
            PsT[c + 4][r] = v1.x; PsT[c + 5][r] = v1.y;
            PsT[c + 6][r] = v1.z; PsT[c + 7][r] = v1.w;
        }
        {   // V tile 32k x 64n, direct; 8 floats/thread
            int r = t >> 3, c = (t & 7) << 3;
            const float* src = Vb + (long)(k0 + r) * D_ + n0 + c;
            *(float4*)&Vs[r][c]     = *(const float4*)(src);
            *(float4*)&Vs[r][c + 4] = *(const float4*)(src + 4);
        }
        __syncthreads();

        #pragma unroll
        for (int kk = 0; kk < BK; kk++) {
            float4 a4 = *(const float4*)&PsT[kk][ty << 2];
            float4 b4 = *(const float4*)&Vs[kk][tx << 2];
            float a[4] = {a4.x, a4.y, a4.z, a4.w};
            float bb[4] = {b4.x, b4.y, b4.z, b4.w};
            #pragma unroll
            for (int i = 0; i < 4; i++)
                #pragma unroll
                for (int j = 0; j < 4; j++)
                    acc[i][j] += a[i] * bb[j];
        }
        __syncthreads();
    }

    #pragma unroll
    for (int i = 0; i < 4; i++)
        *(float4*)(C + (long)(m0 + (ty << 2) + i) * D_ + n0 + (tx << 2)) =
            make_float4(acc[i][0], acc[i][1], acc[i][2], acc[i][3]);
}

// ---------------------------------------------------------------------------
extern "C" void kernel_launch(void* const* d_in, const int* in_sizes, int n_in,
                              void* d_out, int out_size)
{
    const float* queries = (const float*)d_in[0];
    const float* keys    = (const float*)d_in[1];
    const float* values  = (const float*)d_in[2];
    const float* Wq      = (const float*)d_in[3];
    const float* Wk      = (const float*)d_in[4];
    const float* wv      = (const float*)d_in[5];
    const int*   valid   = (const int*)d_in[6];
    float* out = (float*)d_out;
    (void)in_sizes; (void)n_in; (void)out_size;

    // 1) both projections (fp32 GEMM -> fp16 [b][h][q], coalesced), one launch
    proj_kernel<<<dim3(H_ / 64, (B_ * Q_) / 64, 2), 256>>>(queries, keys, Wq, Wk);

    // 2) fused tanh scores via tanh.approx.f16x2, masked tiles skipped
    scores_kernel<<<dim3(K_ / 64, Q_ / 32, B_), 256>>>(wv, valid);

    // 3) warp-per-row masked softmax (zeros beyond L)
    softmax_kernel<<<dim3((B_ * Q_) / 8), 256>>>(valid);

    // 4) out = probs @ values, balanced smem/fma tile, masked k-tiles skipped
    av_kernel<<<dim3(D_ / 64, Q_ / 64, B_), 256>>>(values, valid, out);
}